// round 6
// baseline (speedup 1.0000x reference)
#include <cuda_runtime.h>
#include <cstdint>

#define D_MODEL 1024
#define NHEADS  16
#define DK      64
#define BATCH   4
#define SEQ     2048
#define MROWS   (BATCH*SEQ)   // 8192

// Scratch buffers (allocation-free rule: __device__ globals)
__device__ float g_q[MROWS * D_MODEL];
__device__ float g_k[MROWS * D_MODEL];
__device__ float g_v[MROWS * D_MODEL];
__device__ float g_att[MROWS * D_MODEL];
__device__ float g_xr[MROWS * D_MODEL];          // tf32-rounded x
__device__ float g_wr[4 * D_MODEL * D_MODEL];    // tf32-rounded Wq,Wk,Wv,Wo

__device__ __forceinline__ uint32_t f2tf32(float f) {
    uint32_t u;
    asm("cvt.rna.tf32.f32 %0, %1;" : "=r"(u) : "f"(f));
    return u;
}
__device__ __forceinline__ float roundtf(float f) {
    return __uint_as_float(f2tf32(f));
}

// D += A(16x8, row) * B(8x8, col)  -- tf32, fp32 accum
__device__ __forceinline__ void mma1688(float* d, const uint32_t* a, uint32_t b0, uint32_t b1) {
    asm volatile(
        "mma.sync.aligned.m16n8k8.row.col.f32.tf32.tf32.f32 "
        "{%0,%1,%2,%3}, {%4,%5,%6,%7}, {%8,%9}, {%0,%1,%2,%3};"
        : "+f"(d[0]), "+f"(d[1]), "+f"(d[2]), "+f"(d[3])
        : "r"(a[0]), "r"(a[1]), "r"(a[2]), "r"(a[3]), "r"(b0), "r"(b1));
}

__device__ __forceinline__ uint32_t smem_u32(const void* p) {
    uint32_t a;
    asm("{ .reg .u64 t; cvta.to.shared.u64 t, %1; cvt.u32.u64 %0, t; }"
        : "=r"(a) : "l"(p));
    return a;
}
__device__ __forceinline__ void cp_async16(uint32_t saddr, const void* gptr) {
    asm volatile("cp.async.cg.shared.global [%0], [%1], 16;" :: "r"(saddr), "l"(gptr));
}
#define CP_COMMIT() asm volatile("cp.async.commit_group;")
#define CP_WAIT(n)  asm volatile("cp.async.wait_group %0;" :: "n"(n))

// ===========================================================================
// Prep: tf32-round a float array (src untouched)
// ===========================================================================
__global__ void round_tf32(const float4* __restrict__ src, float4* __restrict__ dst, int n4) {
    int i = blockIdx.x * blockDim.x + threadIdx.x;
    if (i < n4) {
        float4 v = src[i];
        float4 o;
        o.x = roundtf(v.x); o.y = roundtf(v.y);
        o.z = roundtf(v.z); o.w = roundtf(v.w);
        dst[i] = o;
    }
}

// ===========================================================================
// GEMM v2: C[m,n] = sum_k A[m,k]*W[n,k] + bias[n]
// 128 threads, 4 warps, warp tile 64x64. Block 128x128, BK=16.
// Both As/Bs K-major stride 20 (bank-bijective frags + cp.async STS).
// Inputs must be tf32-exact (pre-rounded).
// gridDim.z selects (W,bias,C) for fused QKV.
// ===========================================================================
#define GSTR 20

__global__ __launch_bounds__(128, 2)
void gemm_mma2(const float* __restrict__ A,
               const float* __restrict__ W0, const float* __restrict__ W1,
               const float* __restrict__ W2,
               const float* __restrict__ b0p, const float* __restrict__ b1p,
               const float* __restrict__ b2p,
               float* __restrict__ C0, float* __restrict__ C1, float* __restrict__ C2,
               int round_out)
{
    __shared__ uint32_t As[2][128 * GSTR];
    __shared__ uint32_t Bs[2][128 * GSTR];

    const float* W = W0; const float* bias = b0p; float* C = C0;
    if (blockIdx.z == 1) { W = W1; bias = b1p; C = C1; }
    else if (blockIdx.z == 2) { W = W2; bias = b2p; C = C2; }

    const int tid = threadIdx.x;
    const int lane = tid & 31;
    const int wid = tid >> 5;
    const int wm = wid & 1;          // 64-row half
    const int wn = wid >> 1;         // 64-col half
    const int bm = blockIdx.y * 128;
    const int bn = blockIdx.x * 128;
    const int g = lane >> 2;
    const int t = lane & 3;

    const uint32_t as_u = smem_u32(As);
    const uint32_t bs_u = smem_u32(Bs);
    const float* Ag = A + (size_t)(bm + tid) * D_MODEL;
    const float* Wg = W + (size_t)(bn + tid) * D_MODEL;

    auto issue = [&](int kt) {
        const int buf = kt & 1;
        const uint32_t ad = as_u + (buf * 128 * GSTR + tid * GSTR) * 4;
        const uint32_t bd = bs_u + (buf * 128 * GSTR + tid * GSTR) * 4;
        const int k0 = kt * 16;
#pragma unroll
        for (int i = 0; i < 4; i++) {
            cp_async16(ad + i * 16, Ag + k0 + i * 4);
            cp_async16(bd + i * 16, Wg + k0 + i * 4);
        }
        CP_COMMIT();
    };

    float acc[4][8][4];
#pragma unroll
    for (int fm = 0; fm < 4; fm++)
#pragma unroll
        for (int fn = 0; fn < 8; fn++)
#pragma unroll
            for (int j = 0; j < 4; j++) acc[fm][fn][j] = 0.f;

    issue(0);

    const int NKT = D_MODEL / 16;   // 64
    for (int kt = 0; kt < NKT; kt++) {
        const int buf = kt & 1;
        if (kt + 1 < NKT) { issue(kt + 1); CP_WAIT(1); }
        else              { CP_WAIT(0); }
        __syncthreads();

#pragma unroll
        for (int kk = 0; kk < 2; kk++) {
            const int k8 = kk * 8;
            uint32_t a[4][4], b[8][2];
#pragma unroll
            for (int fm = 0; fm < 4; fm++) {
                const int r0 = wm * 64 + fm * 16 + g;
                a[fm][0] = As[buf][r0 * GSTR + k8 + t];
                a[fm][1] = As[buf][(r0 + 8) * GSTR + k8 + t];
                a[fm][2] = As[buf][r0 * GSTR + k8 + t + 4];
                a[fm][3] = As[buf][(r0 + 8) * GSTR + k8 + t + 4];
            }
#pragma unroll
            for (int fn = 0; fn < 8; fn++) {
                const int cn = wn * 64 + fn * 8 + g;
                b[fn][0] = Bs[buf][cn * GSTR + k8 + t];
                b[fn][1] = Bs[buf][cn * GSTR + k8 + t + 4];
            }
#pragma unroll
            for (int fm = 0; fm < 4; fm++)
#pragma unroll
                for (int fn = 0; fn < 8; fn++)
                    mma1688(acc[fm][fn], a[fm], b[fn][0], b[fn][1]);
        }
        __syncthreads();
    }

    // Epilogue: + bias (and optional tf32 rounding for downstream exactness)
#pragma unroll
    for (int fm = 0; fm < 4; fm++) {
        const int row = bm + wm * 64 + fm * 16 + g;
#pragma unroll
        for (int fn = 0; fn < 8; fn++) {
            const int col = bn + wn * 64 + fn * 8 + 2 * t;
            const float bb0 = bias[col];
            const float bb1 = bias[col + 1];
            float v0 = acc[fm][fn][0] + bb0, v1 = acc[fm][fn][1] + bb1;
            float v2 = acc[fm][fn][2] + bb0, v3 = acc[fm][fn][3] + bb1;
            if (round_out) {
                v0 = roundtf(v0); v1 = roundtf(v1);
                v2 = roundtf(v2); v3 = roundtf(v3);
            }
            *(float2*)(C + (size_t)row * D_MODEL + col) = make_float2(v0, v1);
            *(float2*)(C + (size_t)(row + 8) * D_MODEL + col) = make_float2(v2, v3);
        }
    }
}

// ===========================================================================
// Flash attention, causal, tf32 mma.sync. Inputs pre-rounded to tf32-exact;
// loaders are cp.async raw copies. Output tf32-rounded for the O-projection.
// ===========================================================================
#define KP_STR 68
#define V_STR  72

__global__ __launch_bounds__(128, 4)
void attn_mma(const float* __restrict__ Qg, const float* __restrict__ Kg,
              const float* __restrict__ Vg, float* __restrict__ Og)
{
    extern __shared__ uint32_t smu[];
    uint32_t* Ks = smu;                    // [64][KP_STR]
    uint32_t* Vs = smu + 64 * KP_STR;      // [64][V_STR]
    uint32_t* Ps = Vs + 64 * V_STR;        // [64][KP_STR]  (also Q staging)
    const uint32_t ks_u = smem_u32(Ks);
    const uint32_t vs_u = smem_u32(Vs);
    const uint32_t ps_u = smem_u32(Ps);

    const int tid = threadIdx.x;
    const int lane = tid & 31;
    const int wid = tid >> 5;
    const int g = lane >> 2;
    const int t = lane & 3;
    const int qt = (int)gridDim.x - 1 - (int)blockIdx.x;   // heavy tiles first
    const int bh = blockIdx.y;
    const int b = bh >> 4;
    const int h = bh & 15;

    const size_t base = ((size_t)b * SEQ) * D_MODEL + (size_t)h * DK;
    const int q0 = qt * 64;
    const int r0 = wid * 16;

    // ---- stage Q tile into Ps (raw cp.async; q pre-rounded) ----
    for (int idx = tid; idx < 64 * 16; idx += 128) {
        int r = idx >> 4;
        int c = (idx & 15) << 2;
        cp_async16(ps_u + (r * KP_STR + c) * 4,
                   Qg + base + (size_t)(q0 + r) * D_MODEL + c);
    }
    CP_COMMIT();
    CP_WAIT(0);
    __syncthreads();
    uint32_t qf[8][4];
#pragma unroll
    for (int fk = 0; fk < 8; fk++) {
        qf[fk][0] = Ps[(r0 + g) * KP_STR + fk * 8 + t];
        qf[fk][1] = Ps[(r0 + g + 8) * KP_STR + fk * 8 + t];
        qf[fk][2] = Ps[(r0 + g) * KP_STR + fk * 8 + t + 4];
        qf[fk][3] = Ps[(r0 + g + 8) * KP_STR + fk * 8 + t + 4];
    }

    float m_i[2] = {-1e30f, -1e30f};
    float l_i[2] = {0.f, 0.f};
    float o[8][4];
#pragma unroll
    for (int fn = 0; fn < 8; fn++)
#pragma unroll
        for (int j = 0; j < 4; j++) o[fn][j] = 0.f;

    const float sc = 0.125f;   // 1/sqrt(64)

    for (int kt = 0; kt <= qt; kt++) {
        __syncthreads();       // prior iter's Ks/Vs reads + Ps(Q) frag loads done
        const int k0g = kt * 64;
        for (int idx = tid; idx < 64 * 16; idx += 128) {
            int r = idx >> 4;
            int c = (idx & 15) << 2;
            cp_async16(ks_u + (r * KP_STR + c) * 4,
                       Kg + base + (size_t)(k0g + r) * D_MODEL + c);
            cp_async16(vs_u + (r * V_STR + c) * 4,
                       Vg + base + (size_t)(k0g + r) * D_MODEL + c);
        }
        CP_COMMIT();
        CP_WAIT(0);
        __syncthreads();

        // ---- S = Q K^T ----
        float s[8][4];
#pragma unroll
        for (int fn = 0; fn < 8; fn++)
#pragma unroll
            for (int j = 0; j < 4; j++) s[fn][j] = 0.f;

#pragma unroll
        for (int fn = 0; fn < 8; fn++) {
            const uint32_t* krow = &Ks[(fn * 8 + g) * KP_STR];
#pragma unroll
            for (int fk = 0; fk < 8; fk++) {
                uint32_t b0 = krow[fk * 8 + t];
                uint32_t b1 = krow[fk * 8 + t + 4];
                mma1688(s[fn], qf[fk], b0, b1);
            }
        }

        // ---- scale (+ diagonal mask) ----
        if (kt == qt) {
#pragma unroll
            for (int fn = 0; fn < 8; fn++) {
                int c0 = fn * 8 + 2 * t;
#pragma unroll
                for (int j = 0; j < 4; j++) {
                    int col = c0 + (j & 1);
                    int row = r0 + g + ((j >> 1) << 3);
                    s[fn][j] = (col > row) ? -1e30f : s[fn][j] * sc;
                }
            }
        } else {
#pragma unroll
            for (int fn = 0; fn < 8; fn++)
#pragma unroll
                for (int j = 0; j < 4; j++) s[fn][j] *= sc;
        }

        // ---- online softmax (rows g and g+8) ----
#pragma unroll
        for (int h2 = 0; h2 < 2; h2++) {
            const int j0 = h2 * 2;
            float mx = -1e30f;
#pragma unroll
            for (int fn = 0; fn < 8; fn++)
                mx = fmaxf(mx, fmaxf(s[fn][j0], s[fn][j0 + 1]));
            mx = fmaxf(mx, __shfl_xor_sync(0xffffffffu, mx, 1));
            mx = fmaxf(mx, __shfl_xor_sync(0xffffffffu, mx, 2));
            float mn = fmaxf(m_i[h2], mx);
            float al = __expf(m_i[h2] - mn);
            float ls = 0.f;
#pragma unroll
            for (int fn = 0; fn < 8; fn++) {
                float p0 = __expf(s[fn][j0] - mn);
                float p1 = __expf(s[fn][j0 + 1] - mn);
                s[fn][j0] = p0;
                s[fn][j0 + 1] = p1;
                ls += p0 + p1;
            }
            ls += __shfl_xor_sync(0xffffffffu, ls, 1);
            ls += __shfl_xor_sync(0xffffffffu, ls, 2);
            l_i[h2] = l_i[h2] * al + ls;
            m_i[h2] = mn;
#pragma unroll
            for (int fn = 0; fn < 8; fn++) {
                o[fn][j0] *= al;
                o[fn][j0 + 1] *= al;
            }
        }

        // ---- P -> smem (warp-private rows), reload as A-frags ----
#pragma unroll
        for (int fn = 0; fn < 8; fn++) {
            uint32_t* p0 = &Ps[(r0 + g) * KP_STR + fn * 8 + 2 * t];
            p0[0] = f2tf32(s[fn][0]);
            p0[1] = f2tf32(s[fn][1]);
            uint32_t* p1 = &Ps[(r0 + g + 8) * KP_STR + fn * 8 + 2 * t];
            p1[0] = f2tf32(s[fn][2]);
            p1[1] = f2tf32(s[fn][3]);
        }
        __syncwarp();

        uint32_t pf[8][4];
#pragma unroll
        for (int fk = 0; fk < 8; fk++) {
            pf[fk][0] = Ps[(r0 + g) * KP_STR + fk * 8 + t];
            pf[fk][1] = Ps[(r0 + g + 8) * KP_STR + fk * 8 + t];
            pf[fk][2] = Ps[(r0 + g) * KP_STR + fk * 8 + t + 4];
            pf[fk][3] = Ps[(r0 + g + 8) * KP_STR + fk * 8 + t + 4];
        }

        // ---- O += P V ----
#pragma unroll
        for (int fn = 0; fn < 8; fn++) {
#pragma unroll
            for (int fk = 0; fk < 8; fk++) {
                uint32_t b0 = Vs[(fk * 8 + t) * V_STR + fn * 8 + g];
                uint32_t b1 = Vs[(fk * 8 + t + 4) * V_STR + fn * 8 + g];
                mma1688(o[fn], pf[fk], b0, b1);
            }
        }
    }

    // ---- epilogue: normalize, tf32-round (feeds O-projection), store ----
    const float inv0 = 1.f / l_i[0];
    const float inv1 = 1.f / l_i[1];
    const int row0 = q0 + r0 + g;
#pragma unroll
    for (int fn = 0; fn < 8; fn++) {
        const int col = fn * 8 + 2 * t;
        float2 v0 = make_float2(roundtf(o[fn][0] * inv0), roundtf(o[fn][1] * inv0));
        float2 v1 = make_float2(roundtf(o[fn][2] * inv1), roundtf(o[fn][3] * inv1));
        *(float2*)(Og + base + (size_t)row0 * D_MODEL + col) = v0;
        *(float2*)(Og + base + (size_t)(row0 + 8) * D_MODEL + col) = v1;
    }
}

// ---------------------------------------------------------------------------
// Launch
// ---------------------------------------------------------------------------
extern "C" void kernel_launch(void* const* d_in, const int* in_sizes, int n_in,
                              void* d_out, int out_size)
{
    const float* x  = (const float*)d_in[0];
    // d_in[1] = mask (bool) — causal, implemented analytically
    const float* Wq = (const float*)d_in[2];
    const float* bq = (const float*)d_in[3];
    const float* Wk = (const float*)d_in[4];
    const float* bk = (const float*)d_in[5];
    const float* Wv = (const float*)d_in[6];
    const float* bv = (const float*)d_in[7];
    const float* Wo = (const float*)d_in[8];
    const float* bo = (const float*)d_in[9];
    float* out = (float*)d_out;

    float *gq, *gk, *gv, *ga, *gxr, *gwr;
    cudaGetSymbolAddress((void**)&gq, g_q);
    cudaGetSymbolAddress((void**)&gk, g_k);
    cudaGetSymbolAddress((void**)&gv, g_v);
    cudaGetSymbolAddress((void**)&ga, g_att);
    cudaGetSymbolAddress((void**)&gxr, g_xr);
    cudaGetSymbolAddress((void**)&gwr, g_wr);

    const int WSZ = D_MODEL * D_MODEL;   // 1M floats

    // Prep: tf32-round x and the four weight matrices
    round_tf32<<<(MROWS * D_MODEL / 4 + 255) / 256, 256>>>(
        (const float4*)x, (float4*)gxr, MROWS * D_MODEL / 4);
    round_tf32<<<(WSZ / 4 + 255) / 256, 256>>>((const float4*)Wq, (float4*)(gwr + 0 * WSZ), WSZ / 4);
    round_tf32<<<(WSZ / 4 + 255) / 256, 256>>>((const float4*)Wk, (float4*)(gwr + 1 * WSZ), WSZ / 4);
    round_tf32<<<(WSZ / 4 + 255) / 256, 256>>>((const float4*)Wv, (float4*)(gwr + 2 * WSZ), WSZ / 4);
    round_tf32<<<(WSZ / 4 + 255) / 256, 256>>>((const float4*)Wo, (float4*)(gwr + 3 * WSZ), WSZ / 4);

    // Fused Q,K,V projections (grid.z selects weight/bias/output)
    dim3 gqkv(D_MODEL / 128, MROWS / 128, 3);
    gemm_mma2<<<gqkv, 128>>>(gxr,
                             gwr + 0 * WSZ, gwr + 1 * WSZ, gwr + 2 * WSZ,
                             bq, bk, bv,
                             gq, gk, gv, 1);

    const int asmem = (64 * KP_STR + 64 * V_STR + 64 * KP_STR) * (int)sizeof(uint32_t); // 53248
    cudaFuncSetAttribute(attn_mma,
                         cudaFuncAttributeMaxDynamicSharedMemorySize, asmem);
    attn_mma<<<dim3(SEQ / 64, BATCH * NHEADS), 128, asmem>>>(gq, gk, gv, ga);

    // Output projection
    dim3 go(D_MODEL / 128, MROWS / 128, 1);
    gemm_mma2<<<go, 128>>>(ga,
                           gwr + 3 * WSZ, gwr + 3 * WSZ, gwr + 3 * WSZ,
                           bo, bo, bo,
                           out, out, out, 0);
}

// round 11
// speedup vs baseline: 1.1330x; 1.1330x over previous
#include <cuda_runtime.h>
#include <cstdint>

#define D_MODEL 1024
#define NHEADS  16
#define DK      64
#define BATCH   4
#define SEQ     2048
#define MROWS   (BATCH*SEQ)   // 8192

// Scratch buffers (allocation-free rule: __device__ globals)
__device__ float g_q[MROWS * D_MODEL];
__device__ float g_k[MROWS * D_MODEL];
__device__ float g_v[MROWS * D_MODEL];
__device__ float g_att[MROWS * D_MODEL];
__device__ float g_xr[MROWS * D_MODEL];          // tf32-rounded x
__device__ float g_wr[4 * D_MODEL * D_MODEL];    // tf32-rounded Wq,Wk,Wv,Wo

__device__ __forceinline__ uint32_t f2tf32(float f) {
    uint32_t u;
    asm("cvt.rna.tf32.f32 %0, %1;" : "=r"(u) : "f"(f));
    return u;
}
__device__ __forceinline__ float roundtf(float f) {
    return __uint_as_float(f2tf32(f));
}

// D += A(16x8, row) * B(8x8, col)  -- tf32, fp32 accum
__device__ __forceinline__ void mma1688(float* d, const uint32_t* a, uint32_t b0, uint32_t b1) {
    asm volatile(
        "mma.sync.aligned.m16n8k8.row.col.f32.tf32.tf32.f32 "
        "{%0,%1,%2,%3}, {%4,%5,%6,%7}, {%8,%9}, {%0,%1,%2,%3};"
        : "+f"(d[0]), "+f"(d[1]), "+f"(d[2]), "+f"(d[3])
        : "r"(a[0]), "r"(a[1]), "r"(a[2]), "r"(a[3]), "r"(b0), "r"(b1));
}

__device__ __forceinline__ uint32_t smem_u32(const void* p) {
    uint32_t a;
    asm("{ .reg .u64 t; cvta.to.shared.u64 t, %1; cvt.u32.u64 %0, t; }"
        : "=r"(a) : "l"(p));
    return a;
}
__device__ __forceinline__ void cp_async16(uint32_t saddr, const void* gptr) {
    asm volatile("cp.async.cg.shared.global [%0], [%1], 16;" :: "r"(saddr), "l"(gptr));
}
#define CP_COMMIT() asm volatile("cp.async.commit_group;")
#define CP_WAIT(n)  asm volatile("cp.async.wait_group %0;" :: "n"(n))

// ===========================================================================
// Prep (ONE launch): tf32-round x and all four weight matrices.
// ===========================================================================
#define X4   (MROWS * D_MODEL / 4)       // 2M float4
#define W4   (D_MODEL * D_MODEL / 4)     // 256K float4

__global__ void round_all(const float4* __restrict__ x,
                          const float4* __restrict__ Wq, const float4* __restrict__ Wk,
                          const float4* __restrict__ Wv, const float4* __restrict__ Wo,
                          float4* __restrict__ xr, float4* __restrict__ wr)
{
    int i = blockIdx.x * blockDim.x + threadIdx.x;
    const float4* src;
    float4* dst;
    int j;
    if (i < X4) { src = x; dst = xr; j = i; }
    else {
        int k = i - X4;
        int w = k >> 18;                  // 262144 float4 per weight
        j = k & (W4 - 1);
        src = (w == 0) ? Wq : (w == 1) ? Wk : (w == 2) ? Wv : Wo;
        dst = wr + (size_t)w * W4;
    }
    if (i < X4 + 4 * W4) {
        float4 v = src[j];
        float4 o;
        o.x = roundtf(v.x); o.y = roundtf(v.y);
        o.z = roundtf(v.z); o.w = roundtf(v.w);
        dst[j] = o;
    }
}

// ===========================================================================
// GEMM v3: C[m,n] = sum_k A[m,k]*W[n,k] + bias[n]
// 256 threads, 8 warps, warp tile 64x32. Block 128x128, BK=32, 2-stage cp.async.
// Both operands K-major, stride 36 (bank 4g+t bijective). Inputs tf32-exact.
// gridDim.z selects (W,bias,C) for fused QKV.
// ===========================================================================
#define GSTR 36
#define GBUF (128 * GSTR)     // u32 per operand per stage

__global__ __launch_bounds__(256, 2)
void gemm_v3(const float* __restrict__ A,
             const float* __restrict__ W0, const float* __restrict__ W1,
             const float* __restrict__ W2,
             const float* __restrict__ b0p, const float* __restrict__ b1p,
             const float* __restrict__ b2p,
             float* __restrict__ C0, float* __restrict__ C1, float* __restrict__ C2,
             int round_out)
{
    extern __shared__ uint32_t smu[];
    uint32_t* As = smu;              // [2][GBUF]
    uint32_t* Bs = smu + 2 * GBUF;   // [2][GBUF]
    const uint32_t as_u = smem_u32(As);
    const uint32_t bs_u = smem_u32(Bs);

    const float* W = W0; const float* bias = b0p; float* C = C0;
    if (blockIdx.z == 1) { W = W1; bias = b1p; C = C1; }
    else if (blockIdx.z == 2) { W = W2; bias = b2p; C = C2; }

    const int tid = threadIdx.x;
    const int lane = tid & 31;
    const int wid = tid >> 5;
    const int wm = wid & 1;          // 64-row half
    const int wn = wid >> 1;         // 32-col quarter
    const int bm = blockIdx.y * 128;
    const int bn = blockIdx.x * 128;
    const int g = lane >> 2;
    const int t = lane & 3;

    // cp.async mapping: 2 threads per row, 16 floats each
    const int lrow = tid >> 1;
    const int lhalf = (tid & 1) * 16;
    const float* Ag = A + (size_t)(bm + lrow) * D_MODEL + lhalf;
    const float* Wg = W + (size_t)(bn + lrow) * D_MODEL + lhalf;
    const uint32_t a_sb = as_u + (lrow * GSTR + lhalf) * 4;
    const uint32_t b_sb = bs_u + (lrow * GSTR + lhalf) * 4;

    auto issue = [&](int kt) {
        const int buf = kt & 1;
        const int k0 = kt * 32;
        const uint32_t ao = a_sb + buf * GBUF * 4;
        const uint32_t bo = b_sb + buf * GBUF * 4;
#pragma unroll
        for (int i = 0; i < 4; i++) {
            cp_async16(ao + i * 16, Ag + k0 + i * 4);
            cp_async16(bo + i * 16, Wg + k0 + i * 4);
        }
        CP_COMMIT();
    };

    float acc[4][4][4];
#pragma unroll
    for (int fm = 0; fm < 4; fm++)
#pragma unroll
        for (int fn = 0; fn < 4; fn++)
#pragma unroll
            for (int j = 0; j < 4; j++) acc[fm][fn][j] = 0.f;

    issue(0);

    const int NKT = D_MODEL / 32;   // 32
    for (int kt = 0; kt < NKT; kt++) {
        const int buf = kt & 1;
        if (kt + 1 < NKT) { issue(kt + 1); CP_WAIT(1); }
        else              { CP_WAIT(0); }
        __syncthreads();

        const uint32_t* Ab = As + buf * GBUF;
        const uint32_t* Bb = Bs + buf * GBUF;
#pragma unroll
        for (int kk = 0; kk < 4; kk++) {
            const int k8 = kk * 8;
            uint32_t a[4][4], b[4][2];
#pragma unroll
            for (int fm = 0; fm < 4; fm++) {
                const int r0 = wm * 64 + fm * 16 + g;
                a[fm][0] = Ab[r0 * GSTR + k8 + t];
                a[fm][1] = Ab[(r0 + 8) * GSTR + k8 + t];
                a[fm][2] = Ab[r0 * GSTR + k8 + t + 4];
                a[fm][3] = Ab[(r0 + 8) * GSTR + k8 + t + 4];
            }
#pragma unroll
            for (int fn = 0; fn < 4; fn++) {
                const int cn = wn * 32 + fn * 8 + g;
                b[fn][0] = Bb[cn * GSTR + k8 + t];
                b[fn][1] = Bb[cn * GSTR + k8 + t + 4];
            }
#pragma unroll
            for (int fm = 0; fm < 4; fm++)
#pragma unroll
                for (int fn = 0; fn < 4; fn++)
                    mma1688(acc[fm][fn], a[fm], b[fn][0], b[fn][1]);
        }
        __syncthreads();
    }

    // Epilogue: + bias (optional tf32 rounding for downstream exactness)
#pragma unroll
    for (int fm = 0; fm < 4; fm++) {
        const int row = bm + wm * 64 + fm * 16 + g;
#pragma unroll
        for (int fn = 0; fn < 4; fn++) {
            const int col = bn + wn * 32 + fn * 8 + 2 * t;
            const float bb0 = bias[col];
            const float bb1 = bias[col + 1];
            float v0 = acc[fm][fn][0] + bb0, v1 = acc[fm][fn][1] + bb1;
            float v2 = acc[fm][fn][2] + bb0, v3 = acc[fm][fn][3] + bb1;
            if (round_out) {
                v0 = roundtf(v0); v1 = roundtf(v1);
                v2 = roundtf(v2); v3 = roundtf(v3);
            }
            *(float2*)(C + (size_t)row * D_MODEL + col) = make_float2(v0, v1);
            *(float2*)(C + (size_t)(row + 8) * D_MODEL + col) = make_float2(v2, v3);
        }
    }
}

// ===========================================================================
// Flash attention, causal, tf32 mma.sync. Inputs tf32-exact; raw cp.async loads.
// ===========================================================================
#define KP_STR 68
#define V_STR  72

__global__ __launch_bounds__(128, 4)
void attn_mma(const float* __restrict__ Qg, const float* __restrict__ Kg,
              const float* __restrict__ Vg, float* __restrict__ Og)
{
    extern __shared__ uint32_t smua[];
    uint32_t* Ks = smua;                   // [64][KP_STR]
    uint32_t* Vs = smua + 64 * KP_STR;     // [64][V_STR]
    uint32_t* Ps = Vs + 64 * V_STR;        // [64][KP_STR]  (also Q staging)
    const uint32_t ks_u = smem_u32(Ks);
    const uint32_t vs_u = smem_u32(Vs);
    const uint32_t ps_u = smem_u32(Ps);

    const int tid = threadIdx.x;
    const int lane = tid & 31;
    const int wid = tid >> 5;
    const int g = lane >> 2;
    const int t = lane & 3;
    const int qt = (int)gridDim.x - 1 - (int)blockIdx.x;   // heavy tiles first
    const int bh = blockIdx.y;
    const int b = bh >> 4;
    const int h = bh & 15;

    const size_t base = ((size_t)b * SEQ) * D_MODEL + (size_t)h * DK;
    const int q0 = qt * 64;
    const int r0 = wid * 16;

    // ---- stage Q tile (raw cp.async; tf32-exact) ----
    for (int idx = tid; idx < 64 * 16; idx += 128) {
        int r = idx >> 4;
        int c = (idx & 15) << 2;
        cp_async16(ps_u + (r * KP_STR + c) * 4,
                   Qg + base + (size_t)(q0 + r) * D_MODEL + c);
    }
    CP_COMMIT();
    CP_WAIT(0);
    __syncthreads();
    uint32_t qf[8][4];
#pragma unroll
    for (int fk = 0; fk < 8; fk++) {
        qf[fk][0] = Ps[(r0 + g) * KP_STR + fk * 8 + t];
        qf[fk][1] = Ps[(r0 + g + 8) * KP_STR + fk * 8 + t];
        qf[fk][2] = Ps[(r0 + g) * KP_STR + fk * 8 + t + 4];
        qf[fk][3] = Ps[(r0 + g + 8) * KP_STR + fk * 8 + t + 4];
    }

    float m_i[2] = {-1e30f, -1e30f};
    float l_i[2] = {0.f, 0.f};
    float o[8][4];
#pragma unroll
    for (int fn = 0; fn < 8; fn++)
#pragma unroll
        for (int j = 0; j < 4; j++) o[fn][j] = 0.f;

    const float sc = 0.125f;   // 1/sqrt(64)

    for (int kt = 0; kt <= qt; kt++) {
        __syncthreads();
        const int k0g = kt * 64;
        for (int idx = tid; idx < 64 * 16; idx += 128) {
            int r = idx >> 4;
            int c = (idx & 15) << 2;
            cp_async16(ks_u + (r * KP_STR + c) * 4,
                       Kg + base + (size_t)(k0g + r) * D_MODEL + c);
            cp_async16(vs_u + (r * V_STR + c) * 4,
                       Vg + base + (size_t)(k0g + r) * D_MODEL + c);
        }
        CP_COMMIT();
        CP_WAIT(0);
        __syncthreads();

        // ---- S = Q K^T ----
        float s[8][4];
#pragma unroll
        for (int fn = 0; fn < 8; fn++)
#pragma unroll
            for (int j = 0; j < 4; j++) s[fn][j] = 0.f;

#pragma unroll
        for (int fn = 0; fn < 8; fn++) {
            const uint32_t* krow = &Ks[(fn * 8 + g) * KP_STR];
#pragma unroll
            for (int fk = 0; fk < 8; fk++) {
                uint32_t b0 = krow[fk * 8 + t];
                uint32_t b1 = krow[fk * 8 + t + 4];
                mma1688(s[fn], qf[fk], b0, b1);
            }
        }

        // ---- scale (+ diagonal mask) ----
        if (kt == qt) {
#pragma unroll
            for (int fn = 0; fn < 8; fn++) {
                int c0 = fn * 8 + 2 * t;
#pragma unroll
                for (int j = 0; j < 4; j++) {
                    int col = c0 + (j & 1);
                    int row = r0 + g + ((j >> 1) << 3);
                    s[fn][j] = (col > row) ? -1e30f : s[fn][j] * sc;
                }
            }
        } else {
#pragma unroll
            for (int fn = 0; fn < 8; fn++)
#pragma unroll
                for (int j = 0; j < 4; j++) s[fn][j] *= sc;
        }

        // ---- online softmax (rows g and g+8) ----
#pragma unroll
        for (int h2 = 0; h2 < 2; h2++) {
            const int j0 = h2 * 2;
            float mx = -1e30f;
#pragma unroll
            for (int fn = 0; fn < 8; fn++)
                mx = fmaxf(mx, fmaxf(s[fn][j0], s[fn][j0 + 1]));
            mx = fmaxf(mx, __shfl_xor_sync(0xffffffffu, mx, 1));
            mx = fmaxf(mx, __shfl_xor_sync(0xffffffffu, mx, 2));
            float mn = fmaxf(m_i[h2], mx);
            float al = __expf(m_i[h2] - mn);
            float ls = 0.f;
#pragma unroll
            for (int fn = 0; fn < 8; fn++) {
                float p0 = __expf(s[fn][j0] - mn);
                float p1 = __expf(s[fn][j0 + 1] - mn);
                s[fn][j0] = p0;
                s[fn][j0 + 1] = p1;
                ls += p0 + p1;
            }
            ls += __shfl_xor_sync(0xffffffffu, ls, 1);
            ls += __shfl_xor_sync(0xffffffffu, ls, 2);
            l_i[h2] = l_i[h2] * al + ls;
            m_i[h2] = mn;
#pragma unroll
            for (int fn = 0; fn < 8; fn++) {
                o[fn][j0] *= al;
                o[fn][j0 + 1] *= al;
            }
        }

        // ---- P -> smem (warp-private rows), reload as A-frags ----
#pragma unroll
        for (int fn = 0; fn < 8; fn++) {
            uint32_t* p0 = &Ps[(r0 + g) * KP_STR + fn * 8 + 2 * t];
            p0[0] = f2tf32(s[fn][0]);
            p0[1] = f2tf32(s[fn][1]);
            uint32_t* p1 = &Ps[(r0 + g + 8) * KP_STR + fn * 8 + 2 * t];
            p1[0] = f2tf32(s[fn][2]);
            p1[1] = f2tf32(s[fn][3]);
        }
        __syncwarp();

        uint32_t pf[8][4];
#pragma unroll
        for (int fk = 0; fk < 8; fk++) {
            pf[fk][0] = Ps[(r0 + g) * KP_STR + fk * 8 + t];
            pf[fk][1] = Ps[(r0 + g + 8) * KP_STR + fk * 8 + t];
            pf[fk][2] = Ps[(r0 + g) * KP_STR + fk * 8 + t + 4];
            pf[fk][3] = Ps[(r0 + g + 8) * KP_STR + fk * 8 + t + 4];
        }

        // ---- O += P V ----
#pragma unroll
        for (int fn = 0; fn < 8; fn++) {
#pragma unroll
            for (int fk = 0; fk < 8; fk++) {
                uint32_t b0 = Vs[(fk * 8 + t) * V_STR + fn * 8 + g];
                uint32_t b1 = Vs[(fk * 8 + t + 4) * V_STR + fn * 8 + g];
                mma1688(o[fn], pf[fk], b0, b1);
            }
        }
    }

    // ---- epilogue: normalize, tf32-round (feeds O-projection), store ----
    const float inv0 = 1.f / l_i[0];
    const float inv1 = 1.f / l_i[1];
    const int row0 = q0 + r0 + g;
#pragma unroll
    for (int fn = 0; fn < 8; fn++) {
        const int col = fn * 8 + 2 * t;
        float2 v0 = make_float2(roundtf(o[fn][0] * inv0), roundtf(o[fn][1] * inv0));
        float2 v1 = make_float2(roundtf(o[fn][2] * inv1), roundtf(o[fn][3] * inv1));
        *(float2*)(Og + base + (size_t)row0 * D_MODEL + col) = v0;
        *(float2*)(Og + base + (size_t)(row0 + 8) * D_MODEL + col) = v1;
    }
}

// ---------------------------------------------------------------------------
// Launch
// ---------------------------------------------------------------------------
extern "C" void kernel_launch(void* const* d_in, const int* in_sizes, int n_in,
                              void* d_out, int out_size)
{
    const float* x  = (const float*)d_in[0];
    // d_in[1] = mask (bool) — causal, implemented analytically
    const float* Wq = (const float*)d_in[2];
    const float* bq = (const float*)d_in[3];
    const float* Wk = (const float*)d_in[4];
    const float* bk = (const float*)d_in[5];
    const float* Wv = (const float*)d_in[6];
    const float* bv = (const float*)d_in[7];
    const float* Wo = (const float*)d_in[8];
    const float* bo = (const float*)d_in[9];
    float* out = (float*)d_out;

    float *gq, *gk, *gv, *ga, *gxr, *gwr;
    cudaGetSymbolAddress((void**)&gq, g_q);
    cudaGetSymbolAddress((void**)&gk, g_k);
    cudaGetSymbolAddress((void**)&gv, g_v);
    cudaGetSymbolAddress((void**)&ga, g_att);
    cudaGetSymbolAddress((void**)&gxr, g_xr);
    cudaGetSymbolAddress((void**)&gwr, g_wr);

    const int WSZ = D_MODEL * D_MODEL;   // 1M floats

    // Prep: single launch, tf32-round x + Wq,Wk,Wv,Wo
    const int n4 = X4 + 4 * W4;
    round_all<<<(n4 + 255) / 256, 256>>>(
        (const float4*)x,
        (const float4*)Wq, (const float4*)Wk, (const float4*)Wv, (const float4*)Wo,
        (float4*)gxr, (float4*)gwr);

    const int gsmem = 4 * GBUF * (int)sizeof(uint32_t);   // 73728 B
    cudaFuncSetAttribute(gemm_v3, cudaFuncAttributeMaxDynamicSharedMemorySize, gsmem);

    // Fused Q,K,V projections
    dim3 gqkv(D_MODEL / 128, MROWS / 128, 3);
    gemm_v3<<<gqkv, 256, gsmem>>>(gxr,
                                  gwr + 0 * WSZ, gwr + 1 * WSZ, gwr + 2 * WSZ,
                                  bq, bk, bv,
                                  gq, gk, gv, 1);

    const int asmem = (64 * KP_STR + 64 * V_STR + 64 * KP_STR) * (int)sizeof(uint32_t); // 53248
    cudaFuncSetAttribute(attn_mma,
                         cudaFuncAttributeMaxDynamicSharedMemorySize, asmem);
    attn_mma<<<dim3(SEQ / 64, BATCH * NHEADS), 128, asmem>>>(gq, gk, gv, ga);

    // Output projection
    dim3 go(D_MODEL / 128, MROWS / 128, 1);
    gemm_v3<<<go, 256, gsmem>>>(ga,
                                gwr + 3 * WSZ, gwr + 3 * WSZ, gwr + 3 * WSZ,
                                bo, bo, bo,
                                out, out, out, 0);
}

// round 12
// speedup vs baseline: 1.2452x; 1.0990x over previous
#include <cuda_runtime.h>
#include <cstdint>

#define D_MODEL 1024
#define NHEADS  16
#define DK      64
#define BATCH   4
#define SEQ     2048
#define MROWS   (BATCH*SEQ)   // 8192

// Scratch buffers (allocation-free rule: __device__ globals)
__device__ float g_q[MROWS * D_MODEL];
__device__ float g_k[MROWS * D_MODEL];
__device__ float g_v[MROWS * D_MODEL];
__device__ float g_att[MROWS * D_MODEL];
__device__ float g_xr[MROWS * D_MODEL];          // tf32-rounded x
__device__ float g_wr[4 * D_MODEL * D_MODEL];    // tf32-rounded Wq,Wk,Wv,Wo

__device__ __forceinline__ uint32_t f2tf32(float f) {
    uint32_t u;
    asm("cvt.rna.tf32.f32 %0, %1;" : "=r"(u) : "f"(f));
    return u;
}
__device__ __forceinline__ float roundtf(float f) {
    return __uint_as_float(f2tf32(f));
}

// D += A(16x8, row) * B(8x8, col)  -- tf32, fp32 accum
__device__ __forceinline__ void mma1688(float* d, const uint32_t* a, uint32_t b0, uint32_t b1) {
    asm volatile(
        "mma.sync.aligned.m16n8k8.row.col.f32.tf32.tf32.f32 "
        "{%0,%1,%2,%3}, {%4,%5,%6,%7}, {%8,%9}, {%0,%1,%2,%3};"
        : "+f"(d[0]), "+f"(d[1]), "+f"(d[2]), "+f"(d[3])
        : "r"(a[0]), "r"(a[1]), "r"(a[2]), "r"(a[3]), "r"(b0), "r"(b1));
}

__device__ __forceinline__ uint32_t smem_u32(const void* p) {
    uint32_t a;
    asm("{ .reg .u64 t; cvta.to.shared.u64 t, %1; cvt.u32.u64 %0, t; }"
        : "=r"(a) : "l"(p));
    return a;
}
__device__ __forceinline__ void cp_async16(uint32_t saddr, const void* gptr) {
    asm volatile("cp.async.cg.shared.global [%0], [%1], 16;" :: "r"(saddr), "l"(gptr));
}
#define CP_COMMIT() asm volatile("cp.async.commit_group;")
#define CP_WAIT(n)  asm volatile("cp.async.wait_group %0;" :: "n"(n))

// ===========================================================================
// Prep (ONE launch): tf32-round x and all four weight matrices.
// ===========================================================================
#define X4   (MROWS * D_MODEL / 4)       // 2M float4
#define W4   (D_MODEL * D_MODEL / 4)     // 256K float4

__global__ void round_all(const float4* __restrict__ x,
                          const float4* __restrict__ Wq, const float4* __restrict__ Wk,
                          const float4* __restrict__ Wv, const float4* __restrict__ Wo,
                          float4* __restrict__ xr, float4* __restrict__ wr)
{
    int i = blockIdx.x * blockDim.x + threadIdx.x;
    const float4* src;
    float4* dst;
    int j;
    if (i < X4) { src = x; dst = xr; j = i; }
    else {
        int k = i - X4;
        int w = k >> 18;
        j = k & (W4 - 1);
        src = (w == 0) ? Wq : (w == 1) ? Wk : (w == 2) ? Wv : Wo;
        dst = wr + (size_t)w * W4;
    }
    if (i < X4 + 4 * W4) {
        float4 v = src[j];
        float4 o;
        o.x = roundtf(v.x); o.y = roundtf(v.y);
        o.z = roundtf(v.z); o.w = roundtf(v.w);
        dst[j] = o;
    }
}

// ===========================================================================
// GEMM v4: C[m,n] = sum_k A[m,k]*W[n,k] + bias[n]
// 256 threads, warp tile 64x32. Block 128x128, BK=32.
// XOR-swizzled smem: off(r,c) = r*32 + (c ^ ((r&7)<<2))  -> 16KB/operand/stage
// 3-stage cp.async pipeline (2-deep lookahead). Inputs tf32-exact.
// ===========================================================================
#define SBUF 4096                 // u32 per operand per stage (128*32)
#define NSTG 3

__global__ __launch_bounds__(256, 2)
void gemm_v4(const float* __restrict__ A,
             const float* __restrict__ W0, const float* __restrict__ W1,
             const float* __restrict__ W2,
             const float* __restrict__ b0p, const float* __restrict__ b1p,
             const float* __restrict__ b2p,
             float* __restrict__ C0, float* __restrict__ C1, float* __restrict__ C2,
             int round_out)
{
    extern __shared__ uint32_t smu[];
    uint32_t* As = smu;                    // [NSTG][SBUF]
    uint32_t* Bs = smu + NSTG * SBUF;      // [NSTG][SBUF]
    const uint32_t as_u = smem_u32(As);
    const uint32_t bs_u = smem_u32(Bs);

    const float* W = W0; const float* bias = b0p; float* C = C0;
    if (blockIdx.z == 1) { W = W1; bias = b1p; C = C1; }
    else if (blockIdx.z == 2) { W = W2; bias = b2p; C = C2; }

    const int tid = threadIdx.x;
    const int lane = tid & 31;
    const int wid = tid >> 5;
    const int wm = wid & 1;          // 64-row half
    const int wn = wid >> 1;         // 32-col quarter
    const int bm = blockIdx.y * 128;
    const int bn = blockIdx.x * 128;
    const int g = lane >> 2;
    const int t = lane & 3;
    const int sw = g << 2;           // frag-load swizzle term

    // cp.async mapping: 2 threads per row, 16 floats each
    const int lrow = tid >> 1;
    const int lhalf = (tid & 1) * 16;
    const float* Ag = A + (size_t)(bm + lrow) * D_MODEL + lhalf;
    const float* Wg = W + (size_t)(bn + lrow) * D_MODEL + lhalf;
    const int rsw = (lrow & 7) << 2;

    auto issue = [&](int kt) {
        const int buf = kt % NSTG;
        const int k0 = kt * 32;
        const uint32_t ao = as_u + (buf * SBUF + lrow * 32) * 4;
        const uint32_t bo = bs_u + (buf * SBUF + lrow * 32) * 4;
#pragma unroll
        for (int i = 0; i < 4; i++) {
            const uint32_t co = (uint32_t)((lhalf + i * 4) ^ rsw) * 4;
            cp_async16(ao + co, Ag + k0 + i * 4);
            cp_async16(bo + co, Wg + k0 + i * 4);
        }
        CP_COMMIT();
    };

    float acc[4][4][4];
#pragma unroll
    for (int fm = 0; fm < 4; fm++)
#pragma unroll
        for (int fn = 0; fn < 4; fn++)
#pragma unroll
            for (int j = 0; j < 4; j++) acc[fm][fn][j] = 0.f;

    issue(0);
    issue(1);

    const int NKT = D_MODEL / 32;   // 32
    for (int kt = 0; kt < NKT; kt++) {
        const int buf = kt % NSTG;
        if (kt + 1 < NKT) { CP_WAIT(1); }
        else              { CP_WAIT(0); }
        __syncthreads();
        if (kt + 2 < NKT) issue(kt + 2);

        const uint32_t* Ab = As + buf * SBUF;
        const uint32_t* Bb = Bs + buf * SBUF;
#pragma unroll
        for (int kk = 0; kk < 4; kk++) {
            const int k8 = kk * 8;
            const int c0 = (k8 + t) ^ sw;
            const int c1 = (k8 + t + 4) ^ sw;
            uint32_t a[4][4], b[4][2];
#pragma unroll
            for (int fm = 0; fm < 4; fm++) {
                const int r0 = wm * 64 + fm * 16 + g;
                a[fm][0] = Ab[r0 * 32 + c0];
                a[fm][1] = Ab[(r0 + 8) * 32 + c0];
                a[fm][2] = Ab[r0 * 32 + c1];
                a[fm][3] = Ab[(r0 + 8) * 32 + c1];
            }
#pragma unroll
            for (int fn = 0; fn < 4; fn++) {
                const int cn = wn * 32 + fn * 8 + g;
                b[fn][0] = Bb[cn * 32 + c0];
                b[fn][1] = Bb[cn * 32 + c1];
            }
#pragma unroll
            for (int fm = 0; fm < 4; fm++)
#pragma unroll
                for (int fn = 0; fn < 4; fn++)
                    mma1688(acc[fm][fn], a[fm], b[fn][0], b[fn][1]);
        }
        __syncthreads();
    }

    // Epilogue
#pragma unroll
    for (int fm = 0; fm < 4; fm++) {
        const int row = bm + wm * 64 + fm * 16 + g;
#pragma unroll
        for (int fn = 0; fn < 4; fn++) {
            const int col = bn + wn * 32 + fn * 8 + 2 * t;
            const float bb0 = bias[col];
            const float bb1 = bias[col + 1];
            float v0 = acc[fm][fn][0] + bb0, v1 = acc[fm][fn][1] + bb1;
            float v2 = acc[fm][fn][2] + bb0, v3 = acc[fm][fn][3] + bb1;
            if (round_out) {
                v0 = roundtf(v0); v1 = roundtf(v1);
                v2 = roundtf(v2); v3 = roundtf(v3);
            }
            *(float2*)(C + (size_t)row * D_MODEL + col) = make_float2(v0, v1);
            *(float2*)(C + (size_t)(row + 8) * D_MODEL + col) = make_float2(v2, v3);
        }
    }
}

// ===========================================================================
// Flash attention v2, causal, tf32 mma.sync. BQ=128 (256 threads, 8 warps of
// 16 q-rows). K/V tiles of 64 shared by all warps; fully-masked tiles skipped
// per-warp (exact). Inputs tf32-exact; raw cp.async loads.
// ===========================================================================
#define KP_STR 68
#define V_STR  72

__global__ __launch_bounds__(256, 2)
void attn_mma2(const float* __restrict__ Qg, const float* __restrict__ Kg,
               const float* __restrict__ Vg, float* __restrict__ Og)
{
    extern __shared__ uint32_t smua[];
    uint32_t* Ks = smua;                   // [64][KP_STR]
    uint32_t* Vs = smua + 64 * KP_STR;     // [64][V_STR]
    uint32_t* Ps = Vs + 64 * V_STR;        // [128][KP_STR]  (also Q staging)
    const uint32_t ks_u = smem_u32(Ks);
    const uint32_t vs_u = smem_u32(Vs);
    const uint32_t ps_u = smem_u32(Ps);

    const int tid = threadIdx.x;
    const int lane = tid & 31;
    const int wid = tid >> 5;
    const int g = lane >> 2;
    const int t = lane & 3;
    const int qt = (int)gridDim.x - 1 - (int)blockIdx.x;   // heavy tiles first
    const int bh = blockIdx.y;
    const int b = bh >> 4;
    const int h = bh & 15;

    const size_t base = ((size_t)b * SEQ) * D_MODEL + (size_t)h * DK;
    const int q0 = qt * 128;
    const int r0 = wid * 16;               // warp's rows within the 128-row tile
    const int wrow = q0 + r0;              // global first row of this warp

    // ---- stage Q tile (128 rows) ----
    for (int idx = tid; idx < 128 * 16; idx += 256) {
        int r = idx >> 4;
        int c = (idx & 15) << 2;
        cp_async16(ps_u + (r * KP_STR + c) * 4,
                   Qg + base + (size_t)(q0 + r) * D_MODEL + c);
    }
    CP_COMMIT();
    CP_WAIT(0);
    __syncthreads();
    uint32_t qf[8][4];
#pragma unroll
    for (int fk = 0; fk < 8; fk++) {
        qf[fk][0] = Ps[(r0 + g) * KP_STR + fk * 8 + t];
        qf[fk][1] = Ps[(r0 + g + 8) * KP_STR + fk * 8 + t];
        qf[fk][2] = Ps[(r0 + g) * KP_STR + fk * 8 + t + 4];
        qf[fk][3] = Ps[(r0 + g + 8) * KP_STR + fk * 8 + t + 4];
    }

    float m_i[2] = {-1e30f, -1e30f};
    float l_i[2] = {0.f, 0.f};
    float o[8][4];
#pragma unroll
    for (int fn = 0; fn < 8; fn++)
#pragma unroll
        for (int j = 0; j < 4; j++) o[fn][j] = 0.f;

    const float sc = 0.125f;   // 1/sqrt(64)
    const int nkt = 2 * qt + 2;            // k-tiles of 64 covering [0, q0+128)

    for (int kt = 0; kt < nkt; kt++) {
        __syncthreads();
        const int k0g = kt * 64;
        for (int idx = tid; idx < 64 * 16; idx += 256) {
            int r = idx >> 4;
            int c = (idx & 15) << 2;
            cp_async16(ks_u + (r * KP_STR + c) * 4,
                       Kg + base + (size_t)(k0g + r) * D_MODEL + c);
            cp_async16(vs_u + (r * V_STR + c) * 4,
                       Vg + base + (size_t)(k0g + r) * D_MODEL + c);
        }
        CP_COMMIT();
        CP_WAIT(0);
        __syncthreads();

        if (k0g > wrow + 15) continue;     // fully masked for this warp (exact skip)

        // ---- S = Q K^T ----
        float s[8][4];
#pragma unroll
        for (int fn = 0; fn < 8; fn++)
#pragma unroll
            for (int j = 0; j < 4; j++) s[fn][j] = 0.f;

#pragma unroll
        for (int fn = 0; fn < 8; fn++) {
            const uint32_t* krow = &Ks[(fn * 8 + g) * KP_STR];
#pragma unroll
            for (int fk = 0; fk < 8; fk++) {
                uint32_t b0 = krow[fk * 8 + t];
                uint32_t b1 = krow[fk * 8 + t + 4];
                mma1688(s[fn], qf[fk], b0, b1);
            }
        }

        // ---- scale (+ mask when the tile straddles this warp's diagonal) ----
        if (k0g + 63 > wrow) {
#pragma unroll
            for (int fn = 0; fn < 8; fn++) {
                int c0 = k0g + fn * 8 + 2 * t;
#pragma unroll
                for (int j = 0; j < 4; j++) {
                    int col = c0 + (j & 1);
                    int row = wrow + g + ((j >> 1) << 3);
                    s[fn][j] = (col > row) ? -1e30f : s[fn][j] * sc;
                }
            }
        } else {
#pragma unroll
            for (int fn = 0; fn < 8; fn++)
#pragma unroll
                for (int j = 0; j < 4; j++) s[fn][j] *= sc;
        }

        // ---- online softmax (rows g and g+8) ----
#pragma unroll
        for (int h2 = 0; h2 < 2; h2++) {
            const int j0 = h2 * 2;
            float mx = -1e30f;
#pragma unroll
            for (int fn = 0; fn < 8; fn++)
                mx = fmaxf(mx, fmaxf(s[fn][j0], s[fn][j0 + 1]));
            mx = fmaxf(mx, __shfl_xor_sync(0xffffffffu, mx, 1));
            mx = fmaxf(mx, __shfl_xor_sync(0xffffffffu, mx, 2));
            float mn = fmaxf(m_i[h2], mx);
            float al = __expf(m_i[h2] - mn);
            float ls = 0.f;
#pragma unroll
            for (int fn = 0; fn < 8; fn++) {
                float p0 = __expf(s[fn][j0] - mn);
                float p1 = __expf(s[fn][j0 + 1] - mn);
                s[fn][j0] = p0;
                s[fn][j0 + 1] = p1;
                ls += p0 + p1;
            }
            ls += __shfl_xor_sync(0xffffffffu, ls, 1);
            ls += __shfl_xor_sync(0xffffffffu, ls, 2);
            l_i[h2] = l_i[h2] * al + ls;
            m_i[h2] = mn;
#pragma unroll
            for (int fn = 0; fn < 8; fn++) {
                o[fn][j0] *= al;
                o[fn][j0 + 1] *= al;
            }
        }

        // ---- P -> smem (warp-private rows), reload as A-frags ----
#pragma unroll
        for (int fn = 0; fn < 8; fn++) {
            uint32_t* p0 = &Ps[(r0 + g) * KP_STR + fn * 8 + 2 * t];
            p0[0] = f2tf32(s[fn][0]);
            p0[1] = f2tf32(s[fn][1]);
            uint32_t* p1 = &Ps[(r0 + g + 8) * KP_STR + fn * 8 + 2 * t];
            p1[0] = f2tf32(s[fn][2]);
            p1[1] = f2tf32(s[fn][3]);
        }
        __syncwarp();

        uint32_t pf[8][4];
#pragma unroll
        for (int fk = 0; fk < 8; fk++) {
            pf[fk][0] = Ps[(r0 + g) * KP_STR + fk * 8 + t];
            pf[fk][1] = Ps[(r0 + g + 8) * KP_STR + fk * 8 + t];
            pf[fk][2] = Ps[(r0 + g) * KP_STR + fk * 8 + t + 4];
            pf[fk][3] = Ps[(r0 + g + 8) * KP_STR + fk * 8 + t + 4];
        }

        // ---- O += P V ----
#pragma unroll
        for (int fn = 0; fn < 8; fn++) {
#pragma unroll
            for (int fk = 0; fk < 8; fk++) {
                uint32_t b0 = Vs[(fk * 8 + t) * V_STR + fn * 8 + g];
                uint32_t b1 = Vs[(fk * 8 + t + 4) * V_STR + fn * 8 + g];
                mma1688(o[fn], pf[fk], b0, b1);
            }
        }
    }

    // ---- epilogue: normalize, tf32-round (feeds O-projection), store ----
    const float inv0 = 1.f / l_i[0];
    const float inv1 = 1.f / l_i[1];
    const int row0 = wrow + g;
#pragma unroll
    for (int fn = 0; fn < 8; fn++) {
        const int col = fn * 8 + 2 * t;
        float2 v0 = make_float2(roundtf(o[fn][0] * inv0), roundtf(o[fn][1] * inv0));
        float2 v1 = make_float2(roundtf(o[fn][2] * inv1), roundtf(o[fn][3] * inv1));
        *(float2*)(Og + base + (size_t)row0 * D_MODEL + col) = v0;
        *(float2*)(Og + base + (size_t)(row0 + 8) * D_MODEL + col) = v1;
    }
}

// ---------------------------------------------------------------------------
// Launch
// ---------------------------------------------------------------------------
extern "C" void kernel_launch(void* const* d_in, const int* in_sizes, int n_in,
                              void* d_out, int out_size)
{
    const float* x  = (const float*)d_in[0];
    // d_in[1] = mask (bool) — causal, implemented analytically
    const float* Wq = (const float*)d_in[2];
    const float* bq = (const float*)d_in[3];
    const float* Wk = (const float*)d_in[4];
    const float* bk = (const float*)d_in[5];
    const float* Wv = (const float*)d_in[6];
    const float* bv = (const float*)d_in[7];
    const float* Wo = (const float*)d_in[8];
    const float* bo = (const float*)d_in[9];
    float* out = (float*)d_out;

    float *gq, *gk, *gv, *ga, *gxr, *gwr;
    cudaGetSymbolAddress((void**)&gq, g_q);
    cudaGetSymbolAddress((void**)&gk, g_k);
    cudaGetSymbolAddress((void**)&gv, g_v);
    cudaGetSymbolAddress((void**)&ga, g_att);
    cudaGetSymbolAddress((void**)&gxr, g_xr);
    cudaGetSymbolAddress((void**)&gwr, g_wr);

    const int WSZ = D_MODEL * D_MODEL;   // 1M floats

    // Prep: single launch, tf32-round x + Wq,Wk,Wv,Wo
    const int n4 = X4 + 4 * W4;
    round_all<<<(n4 + 255) / 256, 256>>>(
        (const float4*)x,
        (const float4*)Wq, (const float4*)Wk, (const float4*)Wv, (const float4*)Wo,
        (float4*)gxr, (float4*)gwr);

    const int gsmem = 2 * NSTG * SBUF * (int)sizeof(uint32_t);   // 98304 B
    cudaFuncSetAttribute(gemm_v4, cudaFuncAttributeMaxDynamicSharedMemorySize, gsmem);

    // Fused Q,K,V projections
    dim3 gqkv(D_MODEL / 128, MROWS / 128, 3);
    gemm_v4<<<gqkv, 256, gsmem>>>(gxr,
                                  gwr + 0 * WSZ, gwr + 1 * WSZ, gwr + 2 * WSZ,
                                  bq, bk, bv,
                                  gq, gk, gv, 1);

    const int asmem = (64 * KP_STR + 64 * V_STR + 128 * KP_STR) * (int)sizeof(uint32_t); // 70656
    cudaFuncSetAttribute(attn_mma2,
                         cudaFuncAttributeMaxDynamicSharedMemorySize, asmem);
    attn_mma2<<<dim3(SEQ / 128, BATCH * NHEADS), 256, asmem>>>(gq, gk, gv, ga);

    // Output projection
    dim3 go(D_MODEL / 128, MROWS / 128, 1);
    gemm_v4<<<go, 256, gsmem>>>(ga,
                                gwr + 3 * WSZ, gwr + 3 * WSZ, gwr + 3 * WSZ,
                                bo, bo, bo,
                                out, out, out, 0);
}

// round 13
// speedup vs baseline: 1.2557x; 1.0084x over previous
#include <cuda_runtime.h>
#include <cstdint>

#define D_MODEL 1024
#define NHEADS  16
#define DK      64
#define BATCH   4
#define SEQ     2048
#define MROWS   (BATCH*SEQ)   // 8192

// Scratch buffers (allocation-free rule: __device__ globals)
__device__ float g_q[MROWS * D_MODEL];
__device__ float g_k[MROWS * D_MODEL];
__device__ float g_v[MROWS * D_MODEL];
__device__ float g_att[MROWS * D_MODEL];
__device__ float g_xr[MROWS * D_MODEL];          // tf32-rounded x
__device__ float g_wr[4 * D_MODEL * D_MODEL];    // tf32-rounded Wq,Wk,Wv,Wo

__device__ __forceinline__ uint32_t f2tf32(float f) {
    uint32_t u;
    asm("cvt.rna.tf32.f32 %0, %1;" : "=r"(u) : "f"(f));
    return u;
}
__device__ __forceinline__ float roundtf(float f) {
    return __uint_as_float(f2tf32(f));
}

// D += A(16x8, row) * B(8x8, col)  -- tf32, fp32 accum
__device__ __forceinline__ void mma1688(float* d, const uint32_t* a, uint32_t b0, uint32_t b1) {
    asm volatile(
        "mma.sync.aligned.m16n8k8.row.col.f32.tf32.tf32.f32 "
        "{%0,%1,%2,%3}, {%4,%5,%6,%7}, {%8,%9}, {%0,%1,%2,%3};"
        : "+f"(d[0]), "+f"(d[1]), "+f"(d[2]), "+f"(d[3])
        : "r"(a[0]), "r"(a[1]), "r"(a[2]), "r"(a[3]), "r"(b0), "r"(b1));
}

__device__ __forceinline__ uint32_t smem_u32(const void* p) {
    uint32_t a;
    asm("{ .reg .u64 t; cvta.to.shared.u64 t, %1; cvt.u32.u64 %0, t; }"
        : "=r"(a) : "l"(p));
    return a;
}
__device__ __forceinline__ void cp_async16(uint32_t saddr, const void* gptr) {
    asm volatile("cp.async.cg.shared.global [%0], [%1], 16;" :: "r"(saddr), "l"(gptr));
}
#define CP_COMMIT() asm volatile("cp.async.commit_group;")
#define CP_WAIT(n)  asm volatile("cp.async.wait_group %0;" :: "n"(n))

// ===========================================================================
// Prep (ONE launch): tf32-round x and all four weight matrices.
// ===========================================================================
#define X4   (MROWS * D_MODEL / 4)       // 2M float4
#define W4   (D_MODEL * D_MODEL / 4)     // 256K float4

__global__ void round_all(const float4* __restrict__ x,
                          const float4* __restrict__ Wq, const float4* __restrict__ Wk,
                          const float4* __restrict__ Wv, const float4* __restrict__ Wo,
                          float4* __restrict__ xr, float4* __restrict__ wr)
{
    int i = blockIdx.x * blockDim.x + threadIdx.x;
    const float4* src;
    float4* dst;
    int j;
    if (i < X4) { src = x; dst = xr; j = i; }
    else {
        int k = i - X4;
        int w = k >> 18;
        j = k & (W4 - 1);
        src = (w == 0) ? Wq : (w == 1) ? Wk : (w == 2) ? Wv : Wo;
        dst = wr + (size_t)w * W4;
    }
    if (i < X4 + 4 * W4) {
        float4 v = src[j];
        float4 o;
        o.x = roundtf(v.x); o.y = roundtf(v.y);
        o.z = roundtf(v.z); o.w = roundtf(v.w);
        dst[j] = o;
    }
}

// ===========================================================================
// GEMM v4b: C[m,n] = sum_k A[m,k]*W[n,k] + bias[n]
// 256 threads, warp tile 64x32. Block 128x128, BK=32.
// XOR-swizzled smem, 3-stage cp.async, ONE barrier per k-iter.
// ===========================================================================
#define SBUF 4096                 // u32 per operand per stage (128*32)
#define NSTG 3

__global__ __launch_bounds__(256, 2)
void gemm_v4(const float* __restrict__ A,
             const float* __restrict__ W0, const float* __restrict__ W1,
             const float* __restrict__ W2,
             const float* __restrict__ b0p, const float* __restrict__ b1p,
             const float* __restrict__ b2p,
             float* __restrict__ C0, float* __restrict__ C1, float* __restrict__ C2,
             int round_out)
{
    extern __shared__ uint32_t smu[];
    uint32_t* As = smu;                    // [NSTG][SBUF]
    uint32_t* Bs = smu + NSTG * SBUF;      // [NSTG][SBUF]
    const uint32_t as_u = smem_u32(As);
    const uint32_t bs_u = smem_u32(Bs);

    const float* W = W0; const float* bias = b0p; float* C = C0;
    if (blockIdx.z == 1) { W = W1; bias = b1p; C = C1; }
    else if (blockIdx.z == 2) { W = W2; bias = b2p; C = C2; }

    const int tid = threadIdx.x;
    const int lane = tid & 31;
    const int wid = tid >> 5;
    const int wm = wid & 1;          // 64-row half
    const int wn = wid >> 1;         // 32-col quarter
    const int bm = blockIdx.y * 128;
    const int bn = blockIdx.x * 128;
    const int g = lane >> 2;
    const int t = lane & 3;
    const int sw = g << 2;           // frag-load swizzle term

    // cp.async mapping: 2 threads per row, 16 floats each
    const int lrow = tid >> 1;
    const int lhalf = (tid & 1) * 16;
    const float* Ag = A + (size_t)(bm + lrow) * D_MODEL + lhalf;
    const float* Wg = W + (size_t)(bn + lrow) * D_MODEL + lhalf;
    const int rsw = (lrow & 7) << 2;

    auto issue = [&](int kt) {
        const int buf = kt % NSTG;
        const int k0 = kt * 32;
        const uint32_t ao = as_u + (buf * SBUF + lrow * 32) * 4;
        const uint32_t bo = bs_u + (buf * SBUF + lrow * 32) * 4;
#pragma unroll
        for (int i = 0; i < 4; i++) {
            const uint32_t co = (uint32_t)((lhalf + i * 4) ^ rsw) * 4;
            cp_async16(ao + co, Ag + k0 + i * 4);
            cp_async16(bo + co, Wg + k0 + i * 4);
        }
        CP_COMMIT();
    };

    float acc[4][4][4];
#pragma unroll
    for (int fm = 0; fm < 4; fm++)
#pragma unroll
        for (int fn = 0; fn < 4; fn++)
#pragma unroll
            for (int j = 0; j < 4; j++) acc[fm][fn][j] = 0.f;

    issue(0);
    issue(1);

    const int NKT = D_MODEL / 32;   // 32
    for (int kt = 0; kt < NKT; kt++) {
        const int buf = kt % NSTG;
        if (kt + 1 < NKT) { CP_WAIT(1); }
        else              { CP_WAIT(0); }
        __syncthreads();
        if (kt + 2 < NKT) issue(kt + 2);

        const uint32_t* Ab = As + buf * SBUF;
        const uint32_t* Bb = Bs + buf * SBUF;
#pragma unroll
        for (int kk = 0; kk < 4; kk++) {
            const int k8 = kk * 8;
            const int c0 = (k8 + t) ^ sw;
            const int c1 = (k8 + t + 4) ^ sw;
            uint32_t a[4][4], b[4][2];
#pragma unroll
            for (int fm = 0; fm < 4; fm++) {
                const int r0 = wm * 64 + fm * 16 + g;
                a[fm][0] = Ab[r0 * 32 + c0];
                a[fm][1] = Ab[(r0 + 8) * 32 + c0];
                a[fm][2] = Ab[r0 * 32 + c1];
                a[fm][3] = Ab[(r0 + 8) * 32 + c1];
            }
#pragma unroll
            for (int fn = 0; fn < 4; fn++) {
                const int cn = wn * 32 + fn * 8 + g;
                b[fn][0] = Bb[cn * 32 + c0];
                b[fn][1] = Bb[cn * 32 + c1];
            }
#pragma unroll
            for (int fm = 0; fm < 4; fm++)
#pragma unroll
                for (int fn = 0; fn < 4; fn++)
                    mma1688(acc[fm][fn], a[fm], b[fn][0], b[fn][1]);
        }
        // no trailing barrier: next iter's sync (after its wait) orders
        // this compute against the issue that overwrites this stage.
    }

    // Epilogue
#pragma unroll
    for (int fm = 0; fm < 4; fm++) {
        const int row = bm + wm * 64 + fm * 16 + g;
#pragma unroll
        for (int fn = 0; fn < 4; fn++) {
            const int col = bn + wn * 32 + fn * 8 + 2 * t;
            const float bb0 = bias[col];
            const float bb1 = bias[col + 1];
            float v0 = acc[fm][fn][0] + bb0, v1 = acc[fm][fn][1] + bb1;
            float v2 = acc[fm][fn][2] + bb0, v3 = acc[fm][fn][3] + bb1;
            if (round_out) {
                v0 = roundtf(v0); v1 = roundtf(v1);
                v2 = roundtf(v2); v3 = roundtf(v3);
            }
            *(float2*)(C + (size_t)row * D_MODEL + col) = make_float2(v0, v1);
            *(float2*)(C + (size_t)(row + 8) * D_MODEL + col) = make_float2(v2, v3);
        }
    }
}

// ===========================================================================
// Flash attention v3, causal, tf32 mma.sync. BQ=128, 256 threads.
// K/V double-buffered cp.async: load of tile kt+1 overlaps compute of kt.
// ONE barrier per k-tile. Fully-masked tiles: compute skipped per-warp.
// ===========================================================================
#define KP_STR 68
#define V_STR  72
#define KVSTG  (64 * KP_STR + 64 * V_STR)    // u32 per K/V stage (8960)

__global__ __launch_bounds__(256, 2)
void attn_mma3(const float* __restrict__ Qg, const float* __restrict__ Kg,
               const float* __restrict__ Vg, float* __restrict__ Og)
{
    extern __shared__ uint32_t smua[];
    // [2 stages of (Ks|Vs)] then Ps[128][KP_STR]
    uint32_t* Ps = smua + 2 * KVSTG;
    const uint32_t kv_u = smem_u32(smua);
    const uint32_t ps_u = smem_u32(Ps);

    const int tid = threadIdx.x;
    const int lane = tid & 31;
    const int wid = tid >> 5;
    const int g = lane >> 2;
    const int t = lane & 3;
    const int qt = (int)gridDim.x - 1 - (int)blockIdx.x;   // heavy tiles first
    const int bh = blockIdx.y;
    const int b = bh >> 4;
    const int h = bh & 15;

    const size_t base = ((size_t)b * SEQ) * D_MODEL + (size_t)h * DK;
    const int q0 = qt * 128;
    const int r0 = wid * 16;
    const int wrow = q0 + r0;

    const int nkt = 2 * qt + 2;

    // per-thread K/V loader coords (8 iters of 256 threads over 64x16 float4)
    auto issue_kv = [&](int kt) {
        const int k0g = kt * 64;
        const uint32_t st = kv_u + (uint32_t)(kt & 1) * KVSTG * 4;
        for (int idx = tid; idx < 64 * 16; idx += 256) {
            int r = idx >> 4;
            int c = (idx & 15) << 2;
            cp_async16(st + (r * KP_STR + c) * 4,
                       Kg + base + (size_t)(k0g + r) * D_MODEL + c);
            cp_async16(st + (64 * KP_STR + r * V_STR + c) * 4,
                       Vg + base + (size_t)(k0g + r) * D_MODEL + c);
        }
        CP_COMMIT();
    };

    // ---- stage Q tile (group 1) then K/V tile 0 (group 2) ----
    for (int idx = tid; idx < 128 * 16; idx += 256) {
        int r = idx >> 4;
        int c = (idx & 15) << 2;
        cp_async16(ps_u + (r * KP_STR + c) * 4,
                   Qg + base + (size_t)(q0 + r) * D_MODEL + c);
    }
    CP_COMMIT();
    issue_kv(0);
    CP_WAIT(0);
    __syncthreads();

    uint32_t qf[8][4];
#pragma unroll
    for (int fk = 0; fk < 8; fk++) {
        qf[fk][0] = Ps[(r0 + g) * KP_STR + fk * 8 + t];
        qf[fk][1] = Ps[(r0 + g + 8) * KP_STR + fk * 8 + t];
        qf[fk][2] = Ps[(r0 + g) * KP_STR + fk * 8 + t + 4];
        qf[fk][3] = Ps[(r0 + g + 8) * KP_STR + fk * 8 + t + 4];
    }

    float m_i[2] = {-1e30f, -1e30f};
    float l_i[2] = {0.f, 0.f};
    float o[8][4];
#pragma unroll
    for (int fn = 0; fn < 8; fn++)
#pragma unroll
        for (int j = 0; j < 4; j++) o[fn][j] = 0.f;

    const float sc = 0.125f;   // 1/sqrt(64)

    for (int kt = 0; kt < nkt; kt++) {
        if (kt > 0) {            // stage kt issued in iter kt-1; wait + publish
            CP_WAIT(0);
            __syncthreads();
        }
        if (kt + 1 < nkt) issue_kv(kt + 1);   // overlaps compute below

        const int k0g = kt * 64;
        const uint32_t* Ks = smua + (kt & 1) * KVSTG;
        const uint32_t* Vs = Ks + 64 * KP_STR;

        if (k0g <= wrow + 15) {   // else fully masked for this warp: skip compute
            // ---- S = Q K^T ----
            float s[8][4];
#pragma unroll
            for (int fn = 0; fn < 8; fn++)
#pragma unroll
                for (int j = 0; j < 4; j++) s[fn][j] = 0.f;

#pragma unroll
            for (int fn = 0; fn < 8; fn++) {
                const uint32_t* krow = &Ks[(fn * 8 + g) * KP_STR];
#pragma unroll
                for (int fk = 0; fk < 8; fk++) {
                    uint32_t b0 = krow[fk * 8 + t];
                    uint32_t b1 = krow[fk * 8 + t + 4];
                    mma1688(s[fn], qf[fk], b0, b1);
                }
            }

            // ---- scale (+ mask on diagonal-straddling tiles) ----
            if (k0g + 63 > wrow) {
#pragma unroll
                for (int fn = 0; fn < 8; fn++) {
                    int c0 = k0g + fn * 8 + 2 * t;
#pragma unroll
                    for (int j = 0; j < 4; j++) {
                        int col = c0 + (j & 1);
                        int row = wrow + g + ((j >> 1) << 3);
                        s[fn][j] = (col > row) ? -1e30f : s[fn][j] * sc;
                    }
                }
            } else {
#pragma unroll
                for (int fn = 0; fn < 8; fn++)
#pragma unroll
                    for (int j = 0; j < 4; j++) s[fn][j] *= sc;
            }

            // ---- online softmax (rows g and g+8) ----
#pragma unroll
            for (int h2 = 0; h2 < 2; h2++) {
                const int j0 = h2 * 2;
                float mx = -1e30f;
#pragma unroll
                for (int fn = 0; fn < 8; fn++)
                    mx = fmaxf(mx, fmaxf(s[fn][j0], s[fn][j0 + 1]));
                mx = fmaxf(mx, __shfl_xor_sync(0xffffffffu, mx, 1));
                mx = fmaxf(mx, __shfl_xor_sync(0xffffffffu, mx, 2));
                float mn = fmaxf(m_i[h2], mx);
                float al = __expf(m_i[h2] - mn);
                float ls = 0.f;
#pragma unroll
                for (int fn = 0; fn < 8; fn++) {
                    float p0 = __expf(s[fn][j0] - mn);
                    float p1 = __expf(s[fn][j0 + 1] - mn);
                    s[fn][j0] = p0;
                    s[fn][j0 + 1] = p1;
                    ls += p0 + p1;
                }
                ls += __shfl_xor_sync(0xffffffffu, ls, 1);
                ls += __shfl_xor_sync(0xffffffffu, ls, 2);
                l_i[h2] = l_i[h2] * al + ls;
                m_i[h2] = mn;
#pragma unroll
                for (int fn = 0; fn < 8; fn++) {
                    o[fn][j0] *= al;
                    o[fn][j0 + 1] *= al;
                }
            }

            // ---- P -> smem (warp-private rows), reload as A-frags ----
#pragma unroll
            for (int fn = 0; fn < 8; fn++) {
                uint32_t* p0 = &Ps[(r0 + g) * KP_STR + fn * 8 + 2 * t];
                p0[0] = f2tf32(s[fn][0]);
                p0[1] = f2tf32(s[fn][1]);
                uint32_t* p1 = &Ps[(r0 + g + 8) * KP_STR + fn * 8 + 2 * t];
                p1[0] = f2tf32(s[fn][2]);
                p1[1] = f2tf32(s[fn][3]);
            }
            __syncwarp();

            uint32_t pf[8][4];
#pragma unroll
            for (int fk = 0; fk < 8; fk++) {
                pf[fk][0] = Ps[(r0 + g) * KP_STR + fk * 8 + t];
                pf[fk][1] = Ps[(r0 + g + 8) * KP_STR + fk * 8 + t];
                pf[fk][2] = Ps[(r0 + g) * KP_STR + fk * 8 + t + 4];
                pf[fk][3] = Ps[(r0 + g + 8) * KP_STR + fk * 8 + t + 4];
            }

            // ---- O += P V ----
#pragma unroll
            for (int fn = 0; fn < 8; fn++) {
#pragma unroll
                for (int fk = 0; fk < 8; fk++) {
                    uint32_t b0 = Vs[(fk * 8 + t) * V_STR + fn * 8 + g];
                    uint32_t b1 = Vs[(fk * 8 + t + 4) * V_STR + fn * 8 + g];
                    mma1688(o[fn], pf[fk], b0, b1);
                }
            }
        }
    }

    // ---- epilogue: normalize, tf32-round (feeds O-projection), store ----
    const float inv0 = 1.f / l_i[0];
    const float inv1 = 1.f / l_i[1];
    const int row0 = wrow + g;
#pragma unroll
    for (int fn = 0; fn < 8; fn++) {
        const int col = fn * 8 + 2 * t;
        float2 v0 = make_float2(roundtf(o[fn][0] * inv0), roundtf(o[fn][1] * inv0));
        float2 v1 = make_float2(roundtf(o[fn][2] * inv1), roundtf(o[fn][3] * inv1));
        *(float2*)(Og + base + (size_t)row0 * D_MODEL + col) = v0;
        *(float2*)(Og + base + (size_t)(row0 + 8) * D_MODEL + col) = v1;
    }
}

// ---------------------------------------------------------------------------
// Launch
// ---------------------------------------------------------------------------
extern "C" void kernel_launch(void* const* d_in, const int* in_sizes, int n_in,
                              void* d_out, int out_size)
{
    const float* x  = (const float*)d_in[0];
    // d_in[1] = mask (bool) — causal, implemented analytically
    const float* Wq = (const float*)d_in[2];
    const float* bq = (const float*)d_in[3];
    const float* Wk = (const float*)d_in[4];
    const float* bk = (const float*)d_in[5];
    const float* Wv = (const float*)d_in[6];
    const float* bv = (const float*)d_in[7];
    const float* Wo = (const float*)d_in[8];
    const float* bo = (const float*)d_in[9];
    float* out = (float*)d_out;

    float *gq, *gk, *gv, *ga, *gxr, *gwr;
    cudaGetSymbolAddress((void**)&gq, g_q);
    cudaGetSymbolAddress((void**)&gk, g_k);
    cudaGetSymbolAddress((void**)&gv, g_v);
    cudaGetSymbolAddress((void**)&ga, g_att);
    cudaGetSymbolAddress((void**)&gxr, g_xr);
    cudaGetSymbolAddress((void**)&gwr, g_wr);

    const int WSZ = D_MODEL * D_MODEL;   // 1M floats

    // Prep: single launch, tf32-round x + Wq,Wk,Wv,Wo
    const int n4 = X4 + 4 * W4;
    round_all<<<(n4 + 255) / 256, 256>>>(
        (const float4*)x,
        (const float4*)Wq, (const float4*)Wk, (const float4*)Wv, (const float4*)Wo,
        (float4*)gxr, (float4*)gwr);

    const int gsmem = 2 * NSTG * SBUF * (int)sizeof(uint32_t);   // 98304 B
    cudaFuncSetAttribute(gemm_v4, cudaFuncAttributeMaxDynamicSharedMemorySize, gsmem);

    // Fused Q,K,V projections
    dim3 gqkv(D_MODEL / 128, MROWS / 128, 3);
    gemm_v4<<<gqkv, 256, gsmem>>>(gxr,
                                  gwr + 0 * WSZ, gwr + 1 * WSZ, gwr + 2 * WSZ,
                                  bq, bk, bv,
                                  gq, gk, gv, 1);

    const int asmem = (2 * KVSTG + 128 * KP_STR) * (int)sizeof(uint32_t); // 106496
    cudaFuncSetAttribute(attn_mma3,
                         cudaFuncAttributeMaxDynamicSharedMemorySize, asmem);
    attn_mma3<<<dim3(SEQ / 128, BATCH * NHEADS), 256, asmem>>>(gq, gk, gv, ga);

    // Output projection
    dim3 go(D_MODEL / 128, MROWS / 128, 1);
    gemm_v4<<<go, 256, gsmem>>>(ga,
                                gwr + 3 * WSZ, gwr + 3 * WSZ, gwr + 3 * WSZ,
                                bo, bo, bo,
                                out, out, out, 0);
}